// round 9
// baseline (speedup 1.0000x reference)
#include <cuda_runtime.h>

#define PLANEW   1090            // u64 words per plane: 34*32=1088 +2; 1090 % 16 == 2
#define NTHREADS 128
#define PI_F     3.14159265358979323846f

typedef unsigned long long u64;

// ---- packed f32x2 helpers (sm_100+ PTX; ptxas never emits these from C++) ----
__device__ __forceinline__ u64 pk(float a, float b) {
    u64 r; asm("mov.b64 %0, {%1, %2};" : "=l"(r) : "f"(a), "f"(b)); return r;
}
__device__ __forceinline__ float2 upk(u64 v) {
    float2 r; asm("mov.b64 {%0, %1}, %2;" : "=f"(r.x), "=f"(r.y) : "l"(v)); return r;
}
__device__ __forceinline__ u64 swp(u64 v) {
    u64 r;
    asm("{\n\t.reg .b32 lo, hi;\n\tmov.b64 {lo, hi}, %1;\n\tmov.b64 %0, {hi, lo};\n\t}"
        : "=l"(r) : "l"(v));
    return r;
}
__device__ __forceinline__ u64 f2add(u64 a, u64 b) {
    u64 r; asm("add.rn.f32x2 %0, %1, %2;" : "=l"(r) : "l"(a), "l"(b)); return r;
}
__device__ __forceinline__ u64 f2sub(u64 a, u64 b) {
    u64 r; asm("sub.rn.f32x2 %0, %1, %2;" : "=l"(r) : "l"(a), "l"(b)); return r;
}
__device__ __forceinline__ u64 f2mul(u64 a, u64 b) {
    u64 r; asm("mul.rn.f32x2 %0, %1, %2;" : "=l"(r) : "l"(a), "l"(b)); return r;
}
__device__ __forceinline__ u64 f2fma(u64 a, u64 b, u64 c) {
    u64 r; asm("fma.rn.f32x2 %0, %1, %2, %3;" : "=l"(r) : "l"(a), "l"(b), "l"(c)); return r;
}
// complex multiply of packed (re,im) by twiddle (wc, ws):
//   out = d*(wc,wc) + swap(d)*(-ws, ws)
__device__ __forceinline__ u64 cmul(u64 d, u64 wcc, u64 wss) {
    return f2fma(swp(d), wss, f2mul(d, wcc));
}

// One radix-2 stage on 32 register-resident packed complex elements.
// Pairs (j, j+H), j&H==0; twiddle idx = base_eff + D*k, k=j&(H-1), wrap-free.
// B0=true -> base_eff==0 -> fully constant twiddles (no sincos).
template<int H, int D, bool INV, bool B0>
__device__ __forceinline__ void bf32(u64* X, int base_eff) {
    const int S = D * H;
    const float coef = (INV ? PI_F : -PI_F) / (float)S;
    float w0s, w0c;
    if (B0) { w0c = 1.0f; w0s = 0.0f; }
    else    { __sincosf(coef * (float)base_eff, &w0s, &w0c); }

    constexpr float C16[16] = {
        1.0f, 0.980785280403230449f, 0.923879532511286756f, 0.831469612302545237f,
        0.707106781186547524f, 0.555570233019602225f, 0.382683432365089772f,
        0.195090322016128268f, 0.0f, -0.195090322016128268f, -0.382683432365089772f,
        -0.555570233019602225f, -0.707106781186547524f, -0.831469612302545237f,
        -0.923879532511286756f, -0.980785280403230449f};
    constexpr float S16[16] = {
        0.0f, 0.195090322016128268f, 0.382683432365089772f, 0.555570233019602225f,
        0.707106781186547524f, 0.831469612302545237f, 0.923879532511286756f,
        0.980785280403230449f, 1.0f, 0.980785280403230449f, 0.923879532511286756f,
        0.831469612302545237f, 0.707106781186547524f, 0.555570233019602225f,
        0.382683432365089772f, 0.195090322016128268f};

    #pragma unroll
    for (int k = 0; k < H; ++k) {
        const int t = k * (16 / H);
        const float ckr = C16[t];
        const float cki = INV ? S16[t] : -S16[t];
        const float wc = B0 ? ckr : (w0c * ckr - w0s * cki);
        const float ws = B0 ? cki : (w0s * ckr + w0c * cki);
        const u64 wcc = pk(wc, wc);
        const u64 wss = pk(-ws, ws);
        #pragma unroll
        for (int g = 0; g < 32 / (2 * H); ++g) {
            const int j  = g * 2 * H + k;
            const int j2 = j + H;
            if (!INV) {
                u64 s = f2add(X[j], X[j2]);
                u64 d = f2sub(X[j], X[j2]);
                X[j] = s;
                X[j2] = (B0 && t == 0) ? d : cmul(d, wcc, wss);
            } else {
                u64 tt = (B0 && t == 0) ? X[j2] : cmul(X[j2], wcc, wss);
                X[j2] = f2sub(X[j], tt);
                X[j]  = f2add(X[j], tt);
            }
        }
    }
}

// One CTA: 4 packed complex rows (real rows bi and bi+4096, bi = bc*512 + a0+w).
// Warp w owns row w entirely. Plane layout word(p) = 34*(p>>5) + (p&31):
//   A access: p = r + 32j -> word = plane + r + 34j   (LDS.64, conflict-free)
//   C access: p = 32r + j -> word = plane + 34r + j   (LDS.128 pairs, conflict-free)
__global__ void __launch_bounds__(NTHREADS, 4)
fbp_kernel(const float* __restrict__ x, const float* __restrict__ filt,
           float* __restrict__ out)
{
    extern __shared__ float2 sm2[];
    u64* __restrict__ sm = reinterpret_cast<u64*>(sm2);

    const int tid = threadIdx.x;
    const int bc  = blockIdx.x >> 7;          // 0..7
    const int a0  = (blockIdx.x & 127) << 2;  // 0..508 step 4

    const float* __restrict__ xre = x + bc * 262144 + a0;
    const float* __restrict__ xim = x + (bc + 8) * 262144 + a0;

    // ---- distribute: LDG.128 over the CTA's 4 a-values, scatter packed ----
    #pragma unroll
    for (int k = 0; k < 4; ++k) {
        int s = tid + NTHREADS * k;      // 0..511
        float4 re4 = *reinterpret_cast<const float4*>(xre + s * 512);
        float4 im4 = *reinterpret_cast<const float4*>(xim + s * 512);
        int wd = 34 * (s >> 5) + (s & 31);
        sm[0 * PLANEW + wd] = pk(re4.x, im4.x);
        sm[1 * PLANEW + wd] = pk(re4.y, im4.y);
        sm[2 * PLANEW + wd] = pk(re4.z, im4.z);
        sm[3 * PLANEW + wd] = pk(re4.w, im4.w);
    }
    __syncthreads();

    const int w = tid >> 5;          // warp = plane/row
    const int r = tid & 31;
    const int plane = w * PLANEW;
    const int bA = plane + r;        // + 34j
    const int bC = plane + 34 * r;   // + j (16B aligned: 34r even)

    u64 X[32];

    // ======== phase A: p = r + 32j, strides 512,256,128,64,32 ========
    #pragma unroll
    for (int j = 0; j < 16; ++j)     // p = r + 32j < 512
        X[j] = sm[bA + 34 * j];
    #pragma unroll
    for (int j = 16; j < 32; ++j) X[j] = 0ULL;
    bf32<16, 32, false, false>(X, r);
    bf32< 8, 32, false, false>(X, r);
    bf32< 4, 32, false, false>(X, r);
    bf32< 2, 32, false, false>(X, r);
    bf32< 1, 32, false, false>(X, r);
    #pragma unroll
    for (int j = 0; j < 32; ++j) sm[bA + 34 * j] = X[j];
    __syncwarp();

    // ======== phase C: p = 32r + j, fwd 16..1, filter, inv 1..16 ========
    {
        const ulonglong2* __restrict__ cp =
            reinterpret_cast<const ulonglong2*>(sm + bC);
        #pragma unroll
        for (int h = 0; h < 16; ++h) {
            ulonglong2 v = cp[h];
            X[2*h] = v.x; X[2*h+1] = v.y;
        }
    }
    bf32<16, 1, false, true>(X, 0);
    bf32< 8, 1, false, true>(X, 0);
    bf32< 4, 1, false, true>(X, 0);
    bf32< 2, 1, false, true>(X, 0);
    bf32< 1, 1, false, true>(X, 0);
    {
        const float4* __restrict__ f4 =
            reinterpret_cast<const float4*>(filt + 32 * r);
        #pragma unroll
        for (int i = 0; i < 8; ++i) {   // bit-reversed-domain filter; fold 1/n
            float4 f = __ldg(f4 + i);
            X[4*i+0] = f2mul(X[4*i+0], pk(f.x*(1.0f/1024.0f), f.x*(1.0f/1024.0f)));
            X[4*i+1] = f2mul(X[4*i+1], pk(f.y*(1.0f/1024.0f), f.y*(1.0f/1024.0f)));
            X[4*i+2] = f2mul(X[4*i+2], pk(f.z*(1.0f/1024.0f), f.z*(1.0f/1024.0f)));
            X[4*i+3] = f2mul(X[4*i+3], pk(f.w*(1.0f/1024.0f), f.w*(1.0f/1024.0f)));
        }
    }
    bf32< 1, 1, true, true>(X, 0);
    bf32< 2, 1, true, true>(X, 0);
    bf32< 4, 1, true, true>(X, 0);
    bf32< 8, 1, true, true>(X, 0);
    bf32<16, 1, true, true>(X, 0);
    {
        ulonglong2* __restrict__ cp = reinterpret_cast<ulonglong2*>(sm + bC);
        #pragma unroll
        for (int h = 0; h < 16; ++h) {
            ulonglong2 v; v.x = X[2*h]; v.y = X[2*h+1];
            cp[h] = v;
        }
    }
    __syncwarp();

    // ======== phase A2: p = r + 32j, strides 32,64,128,256,512 ========
    #pragma unroll
    for (int j = 0; j < 32; ++j) X[j] = sm[bA + 34 * j];
    bf32< 1, 32, true, false>(X, r);
    bf32< 2, 32, true, false>(X, r);
    bf32< 4, 32, true, false>(X, r);
    bf32< 8, 32, true, false>(X, r);
    bf32<16, 32, true, false>(X, r);
    #pragma unroll
    for (int j = 0; j < 16; ++j)     // only p < 512 emitted
        sm[bA + 34 * j] = X[j];
    __syncthreads();

    // ---- gather: planes -> STG.128 over the CTA's 4 bi per s ----
    float* __restrict__ ore = out + bc * 512 + a0;
    float* __restrict__ oim = out + (bc + 8) * 512 + a0;
    #pragma unroll
    for (int k = 0; k < 4; ++k) {
        int s  = tid + NTHREADS * k;
        int wd = 34 * (s >> 5) + (s & 31);
        float2 v0 = upk(sm[0 * PLANEW + wd]);
        float2 v1 = upk(sm[1 * PLANEW + wd]);
        float2 v2 = upk(sm[2 * PLANEW + wd]);
        float2 v3 = upk(sm[3 * PLANEW + wd]);
        *reinterpret_cast<float4*>(ore + s * 8192) =
            make_float4(v0.x, v1.x, v2.x, v3.x);
        *reinterpret_cast<float4*>(oim + s * 8192) =
            make_float4(v0.y, v1.y, v2.y, v3.y);
    }
}

extern "C" void kernel_launch(void* const* d_in, const int* in_sizes, int n_in,
                              void* d_out, int out_size) {
    (void)in_sizes; (void)n_in; (void)out_size;
    const float* x    = (const float*)d_in[0];
    const float* filt = (const float*)d_in[3];   // fourier_filter_br
    float* out = (float*)d_out;

    const size_t smem_bytes = (size_t)4 * PLANEW * sizeof(u64);  // 34880
    cudaFuncSetAttribute(fbp_kernel, cudaFuncAttributeMaxDynamicSharedMemorySize,
                         (int)smem_bytes);
    fbp_kernel<<<1024, NTHREADS, smem_bytes>>>(x, filt, out);
}

// round 10
// speedup vs baseline: 1.2613x; 1.2613x over previous
#include <cuda_runtime.h>

#define PLANEW   1090            // u64 words per plane: 34*32=1088 +2; 1090 % 16 == 2
#define NTHREADS 256
#define PI_F     3.14159265358979323846f

typedef unsigned long long u64;

// ---- packed f32x2 helpers (sm_100+ PTX; ptxas never emits these from C++) ----
__device__ __forceinline__ u64 pk(float a, float b) {
    u64 r; asm("mov.b64 %0, {%1, %2};" : "=l"(r) : "f"(a), "f"(b)); return r;
}
__device__ __forceinline__ float2 upk(u64 v) {
    float2 r; asm("mov.b64 {%0, %1}, %2;" : "=f"(r.x), "=f"(r.y) : "l"(v)); return r;
}
__device__ __forceinline__ u64 swp(u64 v) {
    u64 r;
    asm("{\n\t.reg .b32 lo, hi;\n\tmov.b64 {lo, hi}, %1;\n\tmov.b64 %0, {hi, lo};\n\t}"
        : "=l"(r) : "l"(v));
    return r;
}
__device__ __forceinline__ u64 f2add(u64 a, u64 b) {
    u64 r; asm("add.rn.f32x2 %0, %1, %2;" : "=l"(r) : "l"(a), "l"(b)); return r;
}
__device__ __forceinline__ u64 f2sub(u64 a, u64 b) {
    u64 r; asm("sub.rn.f32x2 %0, %1, %2;" : "=l"(r) : "l"(a), "l"(b)); return r;
}
__device__ __forceinline__ u64 f2mul(u64 a, u64 b) {
    u64 r; asm("mul.rn.f32x2 %0, %1, %2;" : "=l"(r) : "l"(a), "l"(b)); return r;
}
__device__ __forceinline__ u64 f2fma(u64 a, u64 b, u64 c) {
    u64 r; asm("fma.rn.f32x2 %0, %1, %2, %3;" : "=l"(r) : "l"(a), "l"(b), "l"(c)); return r;
}
// complex multiply of packed (re,im) by twiddle (wc, ws): d*(wc,wc) + swap(d)*(-ws,ws)
__device__ __forceinline__ u64 cmul(u64 d, u64 wcc, u64 wss) {
    return f2fma(swp(d), wss, f2mul(d, wcc));
}

// One radix-2 stage on 32 register-resident packed complex elements.
// Pairs (j, j+H), j&H==0; twiddle idx = base_eff + D*k, k=j&(H-1), wrap-free.
// B0=true -> base_eff==0 -> fully constant twiddles (no sincos).
template<int H, int D, bool INV, bool B0>
__device__ __forceinline__ void bf32(u64* X, int base_eff) {
    const int S = D * H;
    const float coef = (INV ? PI_F : -PI_F) / (float)S;
    float w0s, w0c;
    if (B0) { w0c = 1.0f; w0s = 0.0f; }
    else    { __sincosf(coef * (float)base_eff, &w0s, &w0c); }

    constexpr float C16[16] = {
        1.0f, 0.980785280403230449f, 0.923879532511286756f, 0.831469612302545237f,
        0.707106781186547524f, 0.555570233019602225f, 0.382683432365089772f,
        0.195090322016128268f, 0.0f, -0.195090322016128268f, -0.382683432365089772f,
        -0.555570233019602225f, -0.707106781186547524f, -0.831469612302545237f,
        -0.923879532511286756f, -0.980785280403230449f};
    constexpr float S16[16] = {
        0.0f, 0.195090322016128268f, 0.382683432365089772f, 0.555570233019602225f,
        0.707106781186547524f, 0.831469612302545237f, 0.923879532511286756f,
        0.980785280403230449f, 1.0f, 0.980785280403230449f, 0.923879532511286756f,
        0.831469612302545237f, 0.707106781186547524f, 0.555570233019602225f,
        0.382683432365089772f, 0.195090322016128268f};

    #pragma unroll
    for (int k = 0; k < H; ++k) {
        const int t = k * (16 / H);
        const float ckr = C16[t];
        const float cki = INV ? S16[t] : -S16[t];
        const float wc = B0 ? ckr : (w0c * ckr - w0s * cki);
        const float ws = B0 ? cki : (w0s * ckr + w0c * cki);
        const u64 wcc = pk(wc, wc);
        const u64 wss = pk(-ws, ws);
        #pragma unroll
        for (int g = 0; g < 32 / (2 * H); ++g) {
            const int j  = g * 2 * H + k;
            const int j2 = j + H;
            if (!INV) {
                u64 s = f2add(X[j], X[j2]);
                u64 d = f2sub(X[j], X[j2]);
                X[j] = s;
                X[j2] = (B0 && t == 0) ? d : cmul(d, wcc, wss);
            } else {
                u64 tt = (B0 && t == 0) ? X[j2] : cmul(X[j2], wcc, wss);
                X[j2] = f2sub(X[j], tt);
                X[j]  = f2add(X[j], tt);
            }
        }
    }
}

// One CTA: 8 packed complex rows (real rows bi and bi+4096, bi = bc*512 + a0+row).
// Phase A/A2 use mapping rowL=tid&7, rL=tid>>3: warp global accesses = 4 full
// 32B sectors; all 20 stages in registers; only TWO smem round trips:
//   A-write (bA layout) -> C-read, C-write (bC layout) -> A2-read.
// Plane layout word(p) = 34*(p>>5) + (p&31):
//   A access: p = rL + 32j -> word = rowL*PLANEW + rL + 34j  (conflict-free)
//   C access: p = 32r + j  -> word = w*PLANEW + 34r + j      (LDS.128, CF)
__global__ void __launch_bounds__(NTHREADS, 2)
fbp_kernel(const float* __restrict__ x, const float* __restrict__ filt,
           float* __restrict__ out)
{
    extern __shared__ float2 sm2[];
    u64* __restrict__ sm = reinterpret_cast<u64*>(sm2);

    const int tid = threadIdx.x;
    const int bc  = blockIdx.x >> 6;         // 0..7
    const int a0  = (blockIdx.x & 63) << 3;  // 0..504 step 8

    const int rowL = tid & 7;    // a-offset within CTA
    const int rL   = tid >> 3;   // 0..31
    const int bAL  = rowL * PLANEW + rL;     // + 34j

    u64 X[32];

    // ======== phase A: direct global load + fwd strides 512..32 ========
    {
        const float* __restrict__ xre = x + bc * 262144 + a0 + rowL;
        const float* __restrict__ xim = x + (bc + 8) * 262144 + a0 + rowL;
        #pragma unroll
        for (int j = 0; j < 16; ++j) {   // p = rL + 32j < 512
            float vr = __ldg(xre + (rL + 32 * j) * 512);
            float vi = __ldg(xim + (rL + 32 * j) * 512);
            X[j] = pk(vr, vi);
        }
        #pragma unroll
        for (int j = 16; j < 32; ++j) X[j] = 0ULL;
    }
    bf32<16, 32, false, false>(X, rL);
    bf32< 8, 32, false, false>(X, rL);
    bf32< 4, 32, false, false>(X, rL);
    bf32< 2, 32, false, false>(X, rL);
    bf32< 1, 32, false, false>(X, rL);
    #pragma unroll
    for (int j = 0; j < 32; ++j) sm[bAL + 34 * j] = X[j];
    __syncthreads();

    // ======== phase C: p = 32r + j, fwd 16..1, filter, inv 1..16 ========
    const int w = tid >> 5;
    const int r = tid & 31;
    const int bC = w * PLANEW + 34 * r;   // 16B aligned (34r even)
    {
        const ulonglong2* __restrict__ cp =
            reinterpret_cast<const ulonglong2*>(sm + bC);
        #pragma unroll
        for (int h = 0; h < 16; ++h) {
            ulonglong2 v = cp[h];
            X[2*h] = v.x; X[2*h+1] = v.y;
        }
    }
    bf32<16, 1, false, true>(X, 0);
    bf32< 8, 1, false, true>(X, 0);
    bf32< 4, 1, false, true>(X, 0);
    bf32< 2, 1, false, true>(X, 0);
    bf32< 1, 1, false, true>(X, 0);
    {
        const float4* __restrict__ f4 =
            reinterpret_cast<const float4*>(filt + 32 * r);
        #pragma unroll
        for (int i = 0; i < 8; ++i) {   // bit-reversed-domain filter; fold 1/n
            float4 f = __ldg(f4 + i);
            X[4*i+0] = f2mul(X[4*i+0], pk(f.x*(1.0f/1024.0f), f.x*(1.0f/1024.0f)));
            X[4*i+1] = f2mul(X[4*i+1], pk(f.y*(1.0f/1024.0f), f.y*(1.0f/1024.0f)));
            X[4*i+2] = f2mul(X[4*i+2], pk(f.z*(1.0f/1024.0f), f.z*(1.0f/1024.0f)));
            X[4*i+3] = f2mul(X[4*i+3], pk(f.w*(1.0f/1024.0f), f.w*(1.0f/1024.0f)));
        }
    }
    bf32< 1, 1, true, true>(X, 0);
    bf32< 2, 1, true, true>(X, 0);
    bf32< 4, 1, true, true>(X, 0);
    bf32< 8, 1, true, true>(X, 0);
    bf32<16, 1, true, true>(X, 0);
    {
        ulonglong2* __restrict__ cp = reinterpret_cast<ulonglong2*>(sm + bC);
        #pragma unroll
        for (int h = 0; h < 16; ++h) {
            ulonglong2 v; v.x = X[2*h]; v.y = X[2*h+1];
            cp[h] = v;
        }
    }
    __syncthreads();

    // ======== phase A2: inv strides 32..512 + direct global store ========
    #pragma unroll
    for (int j = 0; j < 32; ++j) X[j] = sm[bAL + 34 * j];
    bf32< 1, 32, true, false>(X, rL);
    bf32< 2, 32, true, false>(X, rL);
    bf32< 4, 32, true, false>(X, rL);
    bf32< 8, 32, true, false>(X, rL);
    bf32<16, 32, true, false>(X, rL);
    {
        // emit p = rL + 32j, j<16 (p < 512): out[p*8192 + bi], imag at bi+4096
        float* __restrict__ ore = out + bc * 512 + a0 + rowL;
        float* __restrict__ oim = out + (bc + 8) * 512 + a0 + rowL;
        #pragma unroll
        for (int j = 0; j < 16; ++j) {
            float2 v = upk(X[j]);
            ore[(rL + 32 * j) * 8192] = v.x;
            oim[(rL + 32 * j) * 8192] = v.y;
        }
    }
}

extern "C" void kernel_launch(void* const* d_in, const int* in_sizes, int n_in,
                              void* d_out, int out_size) {
    (void)in_sizes; (void)n_in; (void)out_size;
    const float* x    = (const float*)d_in[0];
    const float* filt = (const float*)d_in[3];   // fourier_filter_br
    float* out = (float*)d_out;

    const size_t smem_bytes = (size_t)8 * PLANEW * sizeof(u64);  // 69760
    cudaFuncSetAttribute(fbp_kernel, cudaFuncAttributeMaxDynamicSharedMemorySize,
                         (int)smem_bytes);
    fbp_kernel<<<512, NTHREADS, smem_bytes>>>(x, filt, out);
}

// round 11
// speedup vs baseline: 1.2748x; 1.0107x over previous
#include <cuda_runtime.h>

#define PLANEW   1090            // u64 words per plane: 34*32=1088 +2; 1090 % 16 == 2
#define NTHREADS 256
#define PI_F     3.14159265358979323846f

typedef unsigned long long u64;

// ---- packed f32x2 helpers (sm_100+ PTX; ptxas never emits these from C++) ----
__device__ __forceinline__ u64 pk(float a, float b) {
    u64 r; asm("mov.b64 %0, {%1, %2};" : "=l"(r) : "f"(a), "f"(b)); return r;
}
__device__ __forceinline__ float2 upk(u64 v) {
    float2 r; asm("mov.b64 {%0, %1}, %2;" : "=f"(r.x), "=f"(r.y) : "l"(v)); return r;
}
__device__ __forceinline__ u64 swp(u64 v) {
    u64 r;
    asm("{\n\t.reg .b32 lo, hi;\n\tmov.b64 {lo, hi}, %1;\n\tmov.b64 %0, {hi, lo};\n\t}"
        : "=l"(r) : "l"(v));
    return r;
}
__device__ __forceinline__ u64 f2add(u64 a, u64 b) {
    u64 r; asm("add.rn.f32x2 %0, %1, %2;" : "=l"(r) : "l"(a), "l"(b)); return r;
}
__device__ __forceinline__ u64 f2sub(u64 a, u64 b) {
    u64 r; asm("sub.rn.f32x2 %0, %1, %2;" : "=l"(r) : "l"(a), "l"(b)); return r;
}
__device__ __forceinline__ u64 f2mul(u64 a, u64 b) {
    u64 r; asm("mul.rn.f32x2 %0, %1, %2;" : "=l"(r) : "l"(a), "l"(b)); return r;
}
__device__ __forceinline__ u64 f2fma(u64 a, u64 b, u64 c) {
    u64 r; asm("fma.rn.f32x2 %0, %1, %2, %3;" : "=l"(r) : "l"(a), "l"(b), "l"(c)); return r;
}
// complex multiply of packed (re,im) by twiddle (wc, ws): d*(wc,wc) + swap(d)*(-ws,ws)
__device__ __forceinline__ u64 cmul(u64 d, u64 wcc, u64 wss) {
    return f2fma(swp(d), wss, f2mul(d, wcc));
}

__device__ __constant__ float C16c[16] = {
    1.0f, 0.980785280403230449f, 0.923879532511286756f, 0.831469612302545237f,
    0.707106781186547524f, 0.555570233019602225f, 0.382683432365089772f,
    0.195090322016128268f, 0.0f, -0.195090322016128268f, -0.382683432365089772f,
    -0.555570233019602225f, -0.707106781186547524f, -0.831469612302545237f,
    -0.923879532511286756f, -0.980785280403230449f};
__device__ __constant__ float S16c[16] = {
    0.0f, 0.195090322016128268f, 0.382683432365089772f, 0.555570233019602225f,
    0.707106781186547524f, 0.831469612302545237f, 0.923879532511286756f,
    0.980785280403230449f, 1.0f, 0.980785280403230449f, 0.923879532511286756f,
    0.831469612302545237f, 0.707106781186547524f, 0.555570233019602225f,
    0.382683432365089772f, 0.195090322016128268f};

// generic radix-2 stage on 32 packed complex elements (see earlier rounds).
template<int H, int D, bool INV, bool B0>
__device__ __forceinline__ void bf32(u64* X, int base_eff) {
    const int S = D * H;
    const float coef = (INV ? PI_F : -PI_F) / (float)S;
    float w0s, w0c;
    if (B0) { w0c = 1.0f; w0s = 0.0f; }
    else    { __sincosf(coef * (float)base_eff, &w0s, &w0c); }

    #pragma unroll
    for (int k = 0; k < H; ++k) {
        const int t = k * (16 / H);
        const float ckr = C16c[t];
        const float cki = INV ? S16c[t] : -S16c[t];
        const float wc = B0 ? ckr : (w0c * ckr - w0s * cki);
        const float ws = B0 ? cki : (w0s * ckr + w0c * cki);
        const u64 wcc = pk(wc, wc);
        const u64 wss = pk(-ws, ws);
        #pragma unroll
        for (int g = 0; g < 32 / (2 * H); ++g) {
            const int j  = g * 2 * H + k;
            const int j2 = j + H;
            if (!INV) {
                u64 s = f2add(X[j], X[j2]);
                u64 d = f2sub(X[j], X[j2]);
                X[j] = s;
                if (B0 && t == 0)      X[j2] = d;
                else if (B0 && t == 8) X[j2] = f2mul(swp(d), pk(1.0f, -1.0f));   // w = -i
                else                   X[j2] = cmul(d, wcc, wss);
            } else {
                u64 tt;
                if (B0 && t == 0)      tt = X[j2];
                else if (B0 && t == 8) tt = f2mul(swp(X[j2]), pk(-1.0f, 1.0f)); // w = +i
                else                   tt = cmul(X[j2], wcc, wss);
                X[j2] = f2sub(X[j], tt);
                X[j]  = f2add(X[j], tt);
            }
        }
    }
}

// first forward stage (H=16, D=32) with X[16..31] == 0:
//   X[j] unchanged, X[j+16] = X[j] * w_k  (no add/sub needed)
__device__ __forceinline__ void bf32_first(u64* X, int base_eff) {
    const float coef = -PI_F / 512.0f;
    float w0s, w0c;
    __sincosf(coef * (float)base_eff, &w0s, &w0c);
    #pragma unroll
    for (int k = 0; k < 16; ++k) {
        const float ckr = C16c[k];
        const float cki = -S16c[k];
        const float wc = w0c * ckr - w0s * cki;
        const float ws = w0s * ckr + w0c * cki;
        X[k + 16] = cmul(X[k], pk(wc, wc), pk(-ws, ws));
    }
}

// last inverse stage (H=16, D=32): only X[0..15] survive (p < 512 stored)
__device__ __forceinline__ void bf32_last(u64* X, int base_eff) {
    const float coef = PI_F / 512.0f;
    float w0s, w0c;
    __sincosf(coef * (float)base_eff, &w0s, &w0c);
    #pragma unroll
    for (int k = 0; k < 16; ++k) {
        const float ckr = C16c[k];
        const float cki = S16c[k];
        const float wc = w0c * ckr - w0s * cki;
        const float ws = w0s * ckr + w0c * cki;
        u64 tt = cmul(X[k + 16], pk(wc, wc), pk(-ws, ws));
        X[k] = f2add(X[k], tt);
    }
}

// One CTA: 8 packed complex rows (real rows bi and bi+4096, bi = bc*512 + a0+row).
// Phase A/A2 mapping rowL=tid&7, rL=tid>>3 (warp global ops = 4 full 32B
// sectors); all 20 stages in registers; TWO smem round trips (A<->C transposes).
// Plane layout word(p) = 34*(p>>5) + (p&31):
//   A access: word = rowL*PLANEW + rL + 34j   (LDS/STS.64, conflict-free)
//   C access: word = w*PLANEW + 34r + j       (LDS/STS.128, conflict-free)
__global__ void __launch_bounds__(NTHREADS, 2)
fbp_kernel(const float* __restrict__ x, const float* __restrict__ filt,
           float* __restrict__ out)
{
    extern __shared__ float2 sm2[];
    u64* __restrict__ sm = reinterpret_cast<u64*>(sm2);

    const int tid = threadIdx.x;
    const int bc  = blockIdx.x >> 6;         // 0..7
    const int a0  = (blockIdx.x & 63) << 3;  // 0..504 step 8

    const int rowL = tid & 7;    // a-offset within CTA
    const int rL   = tid >> 3;   // 0..31
    const int bAL  = rowL * PLANEW + rL;     // + 34j

    u64 X[32];

    // ======== phase A: direct global load + fwd strides 512..32 ========
    {
        const float* __restrict__ xre = x + bc * 262144 + a0 + rowL;
        const float* __restrict__ xim = x + (bc + 8) * 262144 + a0 + rowL;
        #pragma unroll
        for (int j = 0; j < 16; ++j) {   // p = rL + 32j < 512
            float vr = __ldg(xre + (rL + 32 * j) * 512);
            float vi = __ldg(xim + (rL + 32 * j) * 512);
            X[j] = pk(vr, vi);
        }
    }
    bf32_first(X, rL);                       // H=16 with zero pad
    bf32< 8, 32, false, false>(X, rL);
    bf32< 4, 32, false, false>(X, rL);
    bf32< 2, 32, false, false>(X, rL);
    bf32< 1, 32, false, false>(X, rL);
    #pragma unroll
    for (int j = 0; j < 32; ++j) sm[bAL + 34 * j] = X[j];
    __syncthreads();

    // ======== phase C: p = 32r + j, fwd 16..1, filter, inv 1..16 ========
    const int w = tid >> 5;
    const int r = tid & 31;
    const int bC = w * PLANEW + 34 * r;   // 16B aligned (34r even)
    {
        const ulonglong2* __restrict__ cp =
            reinterpret_cast<const ulonglong2*>(sm + bC);
        #pragma unroll
        for (int h = 0; h < 16; ++h) {
            ulonglong2 v = cp[h];
            X[2*h] = v.x; X[2*h+1] = v.y;
        }
    }
    bf32<16, 1, false, true>(X, 0);
    bf32< 8, 1, false, true>(X, 0);
    bf32< 4, 1, false, true>(X, 0);
    bf32< 2, 1, false, true>(X, 0);
    bf32< 1, 1, false, true>(X, 0);
    {
        const float4* __restrict__ f4 =
            reinterpret_cast<const float4*>(filt + 32 * r);
        #pragma unroll
        for (int i = 0; i < 8; ++i) {   // bit-reversed-domain filter; fold 1/n
            float4 f = __ldg(f4 + i);
            X[4*i+0] = f2mul(X[4*i+0], pk(f.x*(1.0f/1024.0f), f.x*(1.0f/1024.0f)));
            X[4*i+1] = f2mul(X[4*i+1], pk(f.y*(1.0f/1024.0f), f.y*(1.0f/1024.0f)));
            X[4*i+2] = f2mul(X[4*i+2], pk(f.z*(1.0f/1024.0f), f.z*(1.0f/1024.0f)));
            X[4*i+3] = f2mul(X[4*i+3], pk(f.w*(1.0f/1024.0f), f.w*(1.0f/1024.0f)));
        }
    }
    bf32< 1, 1, true, true>(X, 0);
    bf32< 2, 1, true, true>(X, 0);
    bf32< 4, 1, true, true>(X, 0);
    bf32< 8, 1, true, true>(X, 0);
    bf32<16, 1, true, true>(X, 0);
    {
        ulonglong2* __restrict__ cp = reinterpret_cast<ulonglong2*>(sm + bC);
        #pragma unroll
        for (int h = 0; h < 16; ++h) {
            ulonglong2 v; v.x = X[2*h]; v.y = X[2*h+1];
            cp[h] = v;
        }
    }
    __syncthreads();

    // ======== phase A2: inv strides 32..512 + direct global store ========
    #pragma unroll
    for (int j = 0; j < 32; ++j) X[j] = sm[bAL + 34 * j];
    bf32< 1, 32, true, false>(X, rL);
    bf32< 2, 32, true, false>(X, rL);
    bf32< 4, 32, true, false>(X, rL);
    bf32< 8, 32, true, false>(X, rL);
    bf32_last(X, rL);                        // H=16, upper outputs dead
    {
        // emit p = rL + 32j, j<16 (p < 512): out[p*8192 + bi], imag at bi+4096
        float* __restrict__ ore = out + bc * 512 + a0 + rowL;
        float* __restrict__ oim = out + (bc + 8) * 512 + a0 + rowL;
        #pragma unroll
        for (int j = 0; j < 16; ++j) {
            float2 v = upk(X[j]);
            ore[(rL + 32 * j) * 8192] = v.x;
            oim[(rL + 32 * j) * 8192] = v.y;
        }
    }
}

extern "C" void kernel_launch(void* const* d_in, const int* in_sizes, int n_in,
                              void* d_out, int out_size) {
    (void)in_sizes; (void)n_in; (void)out_size;
    const float* x    = (const float*)d_in[0];
    const float* filt = (const float*)d_in[3];   // fourier_filter_br
    float* out = (float*)d_out;

    const size_t smem_bytes = (size_t)8 * PLANEW * sizeof(u64);  // 69760
    cudaFuncSetAttribute(fbp_kernel, cudaFuncAttributeMaxDynamicSharedMemorySize,
                         (int)smem_bytes);
    fbp_kernel<<<512, NTHREADS, smem_bytes>>>(x, filt, out);
}